// round 1
// baseline (speedup 1.0000x reference)
#include <cuda_runtime.h>
#include <math.h>

#define Bdim 64
#define Sdim 31
#define CTXdim 2048
#define Cdim 512
#define Hdim 8
#define DHdim 64
#define BS (Bdim*Sdim)        // 1984
#define BH (Bdim*Hdim)        // 512
#define SS (Sdim*Sdim)        // 961
#define MCTX (Bdim*CTXdim)    // 131072
#define EPSV 1e-5f
#define INV_SCALE 0.04419417382415922f   // 1/sqrt(512)

// ---------------- scratch (device globals; no runtime allocation) ----------
__device__ float g_xn[BS*Cdim];
__device__ float g_q[BS*Cdim];
__device__ float g_k[BS*Cdim];
__device__ float g_v[BS*Cdim];
__device__ float g_e[BH*SS];
__device__ float g_attn[BH*SS];
__device__ float g_o[BS*Cdim];
__device__ float g_xsa[BS*Cdim];
__device__ float g_qn[BS*Cdim];
__device__ float g_q2[BS*Cdim];
__device__ float g_k2[(size_t)MCTX*Cdim];
__device__ float g_v2[(size_t)MCTX*Cdim];
__device__ float g_attn2[(size_t)BH*Sdim*CTXdim];
__device__ float g_o2[BS*Cdim];
__device__ float g_xca[BS*Cdim];
__device__ float g_t1[BS*Cdim];
__device__ float g_t2[BS*2*Cdim];
__device__ float g_t3[BS*2*Cdim];
__device__ float g_mu[Cdim], g_rstd[Cdim];
__device__ float g_mu2[SS], g_rstd2[SS];

// ---------------- BatchNorm over (B,S) per channel -------------------------
__global__ void bn1_stats(const float* __restrict__ x) {
    int c = blockIdx.x;
    int t = threadIdx.x;
    float s = 0.f, ss = 0.f;
    for (int i = t; i < BS; i += 256) {
        float v = x[(size_t)i*Cdim + c];
        s += v; ss += v*v;
    }
    __shared__ float sha[256], shb[256];
    sha[t] = s; shb[t] = ss; __syncthreads();
    for (int o = 128; o; o >>= 1) {
        if (t < o) { sha[t] += sha[t+o]; shb[t] += shb[t+o]; }
        __syncthreads();
    }
    if (t == 0) {
        float m = sha[0] / (float)BS;
        float var = shb[0] / (float)BS - m*m;
        g_mu[c] = m;
        g_rstd[c] = rsqrtf(var + EPSV);
    }
}

__global__ void bn1_apply(const float* __restrict__ x,
                          const float* __restrict__ g, const float* __restrict__ b) {
    int idx = blockIdx.x * blockDim.x + threadIdx.x;
    if (idx >= BS*Cdim) return;
    int c = idx % Cdim;
    g_xn[idx] = (x[idx] - g_mu[c]) * g_rstd[c] * g[c] + b[c];
}

// ---------------- generic NT GEMM: C[m,n] = A[m,:]·B[n,:] (+bias)(+res) ----
__global__ void gemm_nt(const float* __restrict__ A, const float* __restrict__ Bm,
                        float* __restrict__ C, int M, int N, int K,
                        const float* __restrict__ bias,
                        const float* __restrict__ res) {
    __shared__ float As[16][65];
    __shared__ float Bs[16][65];
    const int bm = blockIdx.y * 64;
    const int bn = blockIdx.x * 64;
    const int tid = threadIdx.x;
    const int tx = tid & 15, ty = tid >> 4;
    float acc[4][4] = {};
    for (int k0 = 0; k0 < K; k0 += 16) {
        #pragma unroll
        for (int i = 0; i < 4; i++) {
            int idx = tid + i*256;
            int r = idx >> 4, c = idx & 15;
            As[c][r] = A[(size_t)(bm + r)*K + k0 + c];
            Bs[c][r] = Bm[(size_t)(bn + r)*K + k0 + c];
        }
        __syncthreads();
        #pragma unroll
        for (int kk = 0; kk < 16; kk++) {
            float a[4], b[4];
            #pragma unroll
            for (int i = 0; i < 4; i++) a[i] = As[kk][ty*4 + i];
            #pragma unroll
            for (int j = 0; j < 4; j++) b[j] = Bs[kk][tx*4 + j];
            #pragma unroll
            for (int i = 0; i < 4; i++)
                #pragma unroll
                for (int j = 0; j < 4; j++)
                    acc[i][j] = fmaf(a[i], b[j], acc[i][j]);
        }
        __syncthreads();
    }
    #pragma unroll
    for (int i = 0; i < 4; i++) {
        int m = bm + ty*4 + i;
        #pragma unroll
        for (int j = 0; j < 4; j++) {
            int n = bn + tx*4 + j;
            float v = acc[i][j];
            if (bias) v += bias[n];
            if (res)  v += res[(size_t)m*N + n];
            C[(size_t)m*N + n] = v;
        }
    }
}

// ---------------- self-attn energy: (31x64)·(31x64)^T per (b,h) ------------
__global__ void sa_energy(const float* __restrict__ q, const float* __restrict__ k,
                          float* __restrict__ e) {
    int bh = blockIdx.x; int b = bh >> 3, h = bh & 7;
    __shared__ float qs[Sdim][DHdim+1], ks[Sdim][DHdim+1];
    int t = threadIdx.x;
    for (int idx = t; idx < Sdim*DHdim; idx += 256) {
        int r = idx >> 6, d = idx & 63;
        qs[r][d] = q[(size_t)(b*Sdim + r)*Cdim + h*DHdim + d];
        ks[r][d] = k[(size_t)(b*Sdim + r)*Cdim + h*DHdim + d];
    }
    __syncthreads();
    for (int idx = t; idx < SS; idx += 256) {
        int i = idx / Sdim, j = idx % Sdim;
        float acc = 0.f;
        #pragma unroll
        for (int d = 0; d < DHdim; d++) acc = fmaf(qs[i][d], ks[j][d], acc);
        e[(size_t)bh*SS + idx] = acc;
    }
}

// ---------------- pre-softmax BatchNorm over (B,H) per (q,k) channel -------
__global__ void bn2_stats(const float* __restrict__ e) {
    int j = blockIdx.x;     // 0..960
    int t = threadIdx.x;
    float s = 0.f, ss = 0.f;
    for (int i = t; i < BH; i += 256) {
        float v = e[(size_t)i*SS + j];
        s += v; ss += v*v;
    }
    __shared__ float sha[256], shb[256];
    sha[t] = s; shb[t] = ss; __syncthreads();
    for (int o = 128; o; o >>= 1) {
        if (t < o) { sha[t] += sha[t+o]; shb[t] += shb[t+o]; }
        __syncthreads();
    }
    if (t == 0) {
        float m = sha[0] / (float)BH;
        float var = shb[0] / (float)BH - m*m;
        g_mu2[j] = m;
        g_rstd2[j] = rsqrtf(var + EPSV);
    }
}

__global__ void sa_softmax(const float* __restrict__ e,
                           const float* __restrict__ pg, const float* __restrict__ pb,
                           float* __restrict__ attn) {
    int row  = blockIdx.x * 8 + (threadIdx.x >> 5);
    int lane = threadIdx.x & 31;
    if (row >= BH*Sdim) return;
    int bh = row / Sdim, i = row % Sdim;
    float val = 0.f, x = -1e30f;
    if (lane < Sdim) {
        int j = i*Sdim + lane;
        float ev = e[(size_t)bh*SS + j];
        val = ((ev - g_mu2[j]) * g_rstd2[j] * pg[j] + pb[j]) * INV_SCALE;
        x = val;
    }
    for (int o = 16; o; o >>= 1) x = fmaxf(x, __shfl_xor_sync(0xffffffffu, x, o));
    float ex = (lane < Sdim) ? expf(val - x) : 0.f;
    float sum = ex;
    for (int o = 16; o; o >>= 1) sum += __shfl_xor_sync(0xffffffffu, sum, o);
    if (lane < Sdim) attn[(size_t)bh*SS + i*Sdim + lane] = ex / sum;
}

__global__ void sa_av(const float* __restrict__ attn, const float* __restrict__ v,
                      float* __restrict__ o) {
    int bh = blockIdx.x; int b = bh >> 3, h = bh & 7;
    __shared__ float as[Sdim][Sdim+1];
    __shared__ float vs[Sdim][DHdim+1];
    int t = threadIdx.x;
    for (int idx = t; idx < SS; idx += 256)
        as[idx / Sdim][idx % Sdim] = attn[(size_t)bh*SS + idx];
    for (int idx = t; idx < Sdim*DHdim; idx += 256) {
        int r = idx >> 6, d = idx & 63;
        vs[r][d] = v[(size_t)(b*Sdim + r)*Cdim + h*DHdim + d];
    }
    __syncthreads();
    for (int idx = t; idx < Sdim*DHdim; idx += 256) {
        int i = idx >> 6, d = idx & 63;
        float acc = 0.f;
        #pragma unroll
        for (int j = 0; j < Sdim; j++) acc = fmaf(as[i][j], vs[j][d], acc);
        o[(size_t)(b*Sdim + i)*Cdim + h*DHdim + d] = acc;
    }
}

// ---------------- LayerNorm (per row), optional SiLU ------------------------
__global__ void ln_kernel(const float* __restrict__ x, float* __restrict__ y,
                          const float* __restrict__ g, const float* __restrict__ bta,
                          int cols, int silu) {
    const int row = blockIdx.x;
    const float* xr = x + (size_t)row*cols;
    float* yr = y + (size_t)row*cols;
    __shared__ float sh[256];
    int t = threadIdx.x;
    float s = 0.f, ss = 0.f;
    for (int c = t; c < cols; c += 256) { float v = xr[c]; s += v; ss += v*v; }
    sh[t] = s; __syncthreads();
    for (int o = 128; o; o >>= 1) { if (t < o) sh[t] += sh[t+o]; __syncthreads(); }
    float mean = sh[0] / (float)cols; __syncthreads();
    sh[t] = ss; __syncthreads();
    for (int o = 128; o; o >>= 1) { if (t < o) sh[t] += sh[t+o]; __syncthreads(); }
    float var = sh[0] / (float)cols - mean*mean;
    float rstd = rsqrtf(var + EPSV);
    for (int c = t; c < cols; c += 256) {
        float v = (xr[c] - mean) * rstd * g[c] + bta[c];
        if (silu) v = v / (1.0f + expf(-v));
        yr[c] = v;
    }
}

// ---------------- cross-attn energy2: (31x64)·(128x64)^T per (b,h,ctx-tile)
__global__ void ca_energy2(const float* __restrict__ q2, const float* __restrict__ k2,
                           float* __restrict__ e2) {
    const int ct = blockIdx.x;   // 16 tiles of 128
    const int h  = blockIdx.y;
    const int b  = blockIdx.z;
    __shared__ float qs[32][DHdim];
    __shared__ float ks[128][DHdim+1];
    const int t = threadIdx.x;
    for (int idx = t; idx < Sdim*DHdim; idx += 256) {
        int r = idx >> 6, d = idx & 63;
        qs[r][d] = q2[(size_t)(b*Sdim + r)*Cdim + h*DHdim + d];
    }
    if (t < DHdim) qs[31][t] = 0.f;   // pad row
    const int c0 = ct * 128;
    for (int idx = t; idx < 128*DHdim; idx += 256) {
        int j = idx >> 6, d = idx & 63;
        ks[j][d] = k2[(size_t)(b*CTXdim + c0 + j)*Cdim + h*DHdim + d];
    }
    __syncthreads();
    const int a  = t >> 5;     // 0..7 -> i-group
    const int bb = t & 31;     // lane -> j base (strided j avoids bank conflicts)
    const int i0 = a * 4;
    float acc[4][4] = {};
    #pragma unroll 8
    for (int kk = 0; kk < DHdim; kk++) {
        float av[4], bv[4];
        #pragma unroll
        for (int ii = 0; ii < 4; ii++) av[ii] = qs[i0 + ii][kk];
        #pragma unroll
        for (int jj = 0; jj < 4; jj++) bv[jj] = ks[bb + 32*jj][kk];
        #pragma unroll
        for (int ii = 0; ii < 4; ii++)
            #pragma unroll
            for (int jj = 0; jj < 4; jj++)
                acc[ii][jj] = fmaf(av[ii], bv[jj], acc[ii][jj]);
    }
    #pragma unroll
    for (int ii = 0; ii < 4; ii++) {
        int i = i0 + ii;
        if (i >= Sdim) break;
        size_t base = ((size_t)(b*Hdim + h)*Sdim + i)*CTXdim + c0;
        #pragma unroll
        for (int jj = 0; jj < 4; jj++) e2[base + bb + 32*jj] = acc[ii][jj];
    }
}

// ---------------- softmax over CTX ------------------------------------------
__global__ void ca_softmax(const float* __restrict__ e2, float* __restrict__ attn2) {
    const int row = blockIdx.x;       // (b*H+h)*S + s
    const float* er = e2 + (size_t)row * CTXdim;
    float* ar = attn2 + (size_t)row * CTXdim;
    __shared__ float sh[256];
    int t = threadIdx.x;
    float mx = -1e30f;
    for (int j = t; j < CTXdim; j += 256) mx = fmaxf(mx, er[j]);
    sh[t] = mx; __syncthreads();
    for (int o = 128; o; o >>= 1) { if (t < o) sh[t] = fmaxf(sh[t], sh[t+o]); __syncthreads(); }
    mx = sh[0] * INV_SCALE; __syncthreads();
    float sum = 0.f;
    for (int j = t; j < CTXdim; j += 256) {
        float v = expf(er[j]*INV_SCALE - mx);
        ar[j] = v;
        sum += v;
    }
    sh[t] = sum; __syncthreads();
    for (int o = 128; o; o >>= 1) { if (t < o) sh[t] += sh[t+o]; __syncthreads(); }
    float inv = 1.0f / sh[0];
    for (int j = t; j < CTXdim; j += 256) ar[j] *= inv;
}

// ---------------- o2 = attn2 (31x2048) · v2 (2048x64) per (b,h) -------------
__global__ void ca_o2(const float* __restrict__ attn2, const float* __restrict__ v2,
                      float* __restrict__ o2) {
    const int bh = blockIdx.x;
    const int b = bh >> 3, h = bh & 7;
    __shared__ float as[32][64];
    __shared__ float vs[64][DHdim+1];
    const int t = threadIdx.x;
    const int a = t >> 5, bb = t & 31;
    const int i0 = a * 4;
    float acc[4][2] = {};
    for (int ct = 0; ct < CTXdim/64; ct++) {
        for (int idx = t; idx < Sdim*64; idx += 256) {
            int r = idx >> 6, j = idx & 63;
            as[r][j] = attn2[((size_t)bh*Sdim + r)*CTXdim + ct*64 + j];
        }
        if (t < 64) as[31][t] = 0.f;   // pad row
        for (int idx = t; idx < 64*64; idx += 256) {
            int j = idx >> 6, d = idx & 63;
            vs[j][d] = v2[(size_t)(b*CTXdim + ct*64 + j)*Cdim + h*DHdim + d];
        }
        __syncthreads();
        #pragma unroll 4
        for (int j = 0; j < 64; j++) {
            float av[4];
            #pragma unroll
            for (int ii = 0; ii < 4; ii++) av[ii] = as[i0 + ii][j];
            float v0 = vs[j][bb], v1 = vs[j][bb + 32];
            #pragma unroll
            for (int ii = 0; ii < 4; ii++) {
                acc[ii][0] = fmaf(av[ii], v0, acc[ii][0]);
                acc[ii][1] = fmaf(av[ii], v1, acc[ii][1]);
            }
        }
        __syncthreads();
    }
    #pragma unroll
    for (int ii = 0; ii < 4; ii++) {
        int i = i0 + ii;
        if (i >= Sdim) break;
        size_t base = (size_t)(b*Sdim + i)*Cdim + h*DHdim;
        o2[base + bb]      = acc[ii][0];
        o2[base + bb + 32] = acc[ii][1];
    }
}

// ---------------- launch ----------------------------------------------------
extern "C" void kernel_launch(void* const* d_in, const int* in_sizes, int n_in,
                              void* d_out, int out_size) {
    const float* queries  = (const float*)d_in[0];
    const float* contexts = (const float*)d_in[1];
    const float* sa_bn_g  = (const float*)d_in[2];
    const float* sa_bn_b  = (const float*)d_in[3];
    const float* sa_q_w   = (const float*)d_in[4];
    const float* sa_k_w   = (const float*)d_in[5];
    const float* sa_v_w   = (const float*)d_in[6];
    const float* sa_out_w = (const float*)d_in[7];
    const float* sa_out_b = (const float*)d_in[8];
    const float* sa_pre_g = (const float*)d_in[9];
    const float* sa_pre_b = (const float*)d_in[10];
    const float* ca_ln_g  = (const float*)d_in[11];
    const float* ca_ln_b  = (const float*)d_in[12];
    const float* ca_q_w   = (const float*)d_in[13];
    const float* ca_k_w   = (const float*)d_in[14];
    const float* ca_v_w   = (const float*)d_in[15];
    const float* ca_out_w = (const float*)d_in[16];
    const float* ca_out_b = (const float*)d_in[17];
    const float* ff_ln1_g = (const float*)d_in[18];
    const float* ff_ln1_b = (const float*)d_in[19];
    const float* ff_w1    = (const float*)d_in[20];
    const float* ff_ln2_g = (const float*)d_in[21];
    const float* ff_ln2_b = (const float*)d_in[22];
    const float* ff_w2    = (const float*)d_in[23];

    float* out = (float*)d_out;
    float* e2  = out + (size_t)BS*Cdim;

    float *xn,*q,*k,*v,*e,*attn,*o,*xsa,*qn,*q2,*k2,*v2,*attn2,*o2,*xca,*t1,*t2,*t3;
    cudaGetSymbolAddress((void**)&xn,   g_xn);
    cudaGetSymbolAddress((void**)&q,    g_q);
    cudaGetSymbolAddress((void**)&k,    g_k);
    cudaGetSymbolAddress((void**)&v,    g_v);
    cudaGetSymbolAddress((void**)&e,    g_e);
    cudaGetSymbolAddress((void**)&attn, g_attn);
    cudaGetSymbolAddress((void**)&o,    g_o);
    cudaGetSymbolAddress((void**)&xsa,  g_xsa);
    cudaGetSymbolAddress((void**)&qn,   g_qn);
    cudaGetSymbolAddress((void**)&q2,   g_q2);
    cudaGetSymbolAddress((void**)&k2,   g_k2);
    cudaGetSymbolAddress((void**)&v2,   g_v2);
    cudaGetSymbolAddress((void**)&attn2,g_attn2);
    cudaGetSymbolAddress((void**)&o2,   g_o2);
    cudaGetSymbolAddress((void**)&xca,  g_xca);
    cudaGetSymbolAddress((void**)&t1,   g_t1);
    cudaGetSymbolAddress((void**)&t2,   g_t2);
    cudaGetSymbolAddress((void**)&t3,   g_t3);

    const dim3 gSmall(Cdim/64, BS/64);       // 8 x 31
    const dim3 gBig(Cdim/64, MCTX/64);       // 8 x 2048
    const dim3 gFF1(2*Cdim/64, BS/64);       // 16 x 31

    // ---- self attention ----
    bn1_stats<<<Cdim, 256>>>(queries);
    bn1_apply<<<(BS*Cdim + 255)/256, 256>>>(queries, sa_bn_g, sa_bn_b);
    gemm_nt<<<gSmall, 256>>>(xn, sa_q_w, q, BS, Cdim, Cdim, nullptr, nullptr);
    gemm_nt<<<gSmall, 256>>>(xn, sa_k_w, k, BS, Cdim, Cdim, nullptr, nullptr);
    gemm_nt<<<gSmall, 256>>>(xn, sa_v_w, v, BS, Cdim, Cdim, nullptr, nullptr);
    sa_energy<<<BH, 256>>>(q, k, e);
    bn2_stats<<<SS, 256>>>(e);
    sa_softmax<<<(BH*Sdim)/8, 256>>>(e, sa_pre_g, sa_pre_b, attn);
    sa_av<<<BH, 256>>>(attn, v, o);
    gemm_nt<<<gSmall, 256>>>(o, sa_out_w, xsa, BS, Cdim, Cdim, sa_out_b, queries);

    // ---- cross attention ----
    ln_kernel<<<BS, 256>>>(xsa, qn, ca_ln_g, ca_ln_b, Cdim, 0);
    gemm_nt<<<gSmall, 256>>>(qn, ca_q_w, q2, BS, Cdim, Cdim, nullptr, nullptr);
    gemm_nt<<<gBig, 256>>>(contexts, ca_k_w, k2, MCTX, Cdim, Cdim, nullptr, nullptr);
    gemm_nt<<<gBig, 256>>>(contexts, ca_v_w, v2, MCTX, Cdim, Cdim, nullptr, nullptr);
    ca_energy2<<<dim3(CTXdim/128, Hdim, Bdim), 256>>>(q2, k2, e2);
    ca_softmax<<<BH*Sdim, 256>>>(e2, attn2);
    ca_o2<<<BH, 256>>>(attn2, v2, o2);
    gemm_nt<<<gSmall, 256>>>(o2, ca_out_w, xca, BS, Cdim, Cdim, ca_out_b, xsa);

    // ---- FFN ----
    ln_kernel<<<BS, 256>>>(xca, t1, ff_ln1_g, ff_ln1_b, Cdim, 1);
    gemm_nt<<<gFF1, 256>>>(t1, ff_w1, t2, BS, 2*Cdim, Cdim, nullptr, nullptr);
    ln_kernel<<<BS, 256>>>(t2, t3, ff_ln2_g, ff_ln2_b, 2*Cdim, 1);
    gemm_nt<<<gSmall, 256>>>(t3, ff_w2, out, BS, Cdim, 2*Cdim, nullptr, xca);
}

// round 3
// speedup vs baseline: 3.0569x; 3.0569x over previous
#include <cuda_runtime.h>
#include <math.h>

#define Bdim 64
#define Sdim 31
#define CTXdim 2048
#define Cdim 512
#define Hdim 8
#define DHdim 64
#define BS (Bdim*Sdim)        // 1984
#define BH (Bdim*Hdim)        // 512
#define SS (Sdim*Sdim)        // 961
#define EPSV 1e-5f
#define INV_SCALE 0.04419417382415922f   // 1/sqrt(512)

// ---------------- scratch (device globals; no runtime allocation) ----------
__device__ float g_xn[BS*Cdim];
__device__ float g_q[BS*Cdim];
__device__ float g_k[BS*Cdim];
__device__ float g_v[BS*Cdim];
__device__ float g_e[BH*SS];
__device__ float g_attn[BH*SS];
__device__ float g_o[BS*Cdim];
__device__ float g_xsa[BS*Cdim];
__device__ float g_qn[BS*Cdim];
__device__ float g_q2[BS*Cdim];
__device__ float g_qk[(size_t)BH*Sdim*Cdim];        // (b,h,s) x 512
__device__ float g_attn2[(size_t)BH*Sdim*CTXdim];
__device__ float g_ov2[(size_t)BS*Hdim*Cdim];       // (b,s) x (h*512+c)
__device__ float g_o2[BS*Cdim];
__device__ float g_xca[BS*Cdim];
__device__ float g_t1[BS*Cdim];
__device__ float g_t2[BS*2*Cdim];
__device__ float g_t3[BS*2*Cdim];
__device__ float g_mu[Cdim], g_rstd[Cdim];
__device__ float g_mu2[SS], g_rstd2[SS];

// ============================================================================
// 128x128x16 double-buffered GEMMs, 8x8 per thread (4+4 fragment split).
// mode 0: C[z*cB + m*ldc + n] (+bias[n]) (+res[z*resB + m*ldc + n])
// mode 1: qk permute:  dst row = (m/31)*248 + z*31 + (m%31), ldc applies
// mode 2: ov2 permute: dst = z*cB + (m%31)*4096 + (m/31)*512 + n
// ============================================================================

#define F4Z make_float4(0.f,0.f,0.f,0.f)

__device__ __forceinline__ void gemm_epilogue(
    float acc[8][8], float* __restrict__ C, int M, int N, int ldc,
    long long cB, const float* __restrict__ bias, const float* __restrict__ res,
    long long resB, int mode, int bm, int bn, int z, int tx, int ty)
{
    const float* resp = res ? res + (size_t)z*resB : nullptr;
    #pragma unroll
    for (int ih = 0; ih < 2; ih++) {
        #pragma unroll
        for (int i = 0; i < 4; i++) {
            int m = bm + ih*64 + ty*4 + i;
            if (m >= M) continue;
            size_t rowbase;
            if (mode == 0)      rowbase = (size_t)z*cB + (size_t)m*ldc;
            else if (mode == 1) rowbase = (size_t)((m/31)*248 + z*31 + (m%31)) * ldc;
            else                rowbase = (size_t)z*cB + (size_t)(m%31)*4096 + (size_t)(m/31)*512;
            #pragma unroll
            for (int jh = 0; jh < 2; jh++) {
                #pragma unroll
                for (int j = 0; j < 4; j++) {
                    int n = bn + jh*64 + tx*4 + j;
                    if (n >= N) continue;
                    float v = acc[ih*4+i][jh*4+j];
                    if (bias) v += bias[n];
                    if (resp) v += resp[(size_t)m*ldc + n];
                    C[rowbase + n] = v;
                }
            }
        }
    }
}

// NT: C[m,n] = sum_k A[m,k]*B[n,k]
__global__ void __launch_bounds__(256, 2) gemm_nt128(
    const float* __restrict__ A, const float* __restrict__ B, float* __restrict__ C,
    int M, int N, int K, int lda, int ldb, int ldc,
    long long aB, long long bB, long long cB,
    const float* __restrict__ bias, const float* __restrict__ res, long long resB,
    int mode)
{
    __shared__ float As[2][16][128];
    __shared__ float Bs[2][16][128];
    const int z = blockIdx.z;
    A += (size_t)z * aB; B += (size_t)z * bB;
    const int bm = blockIdx.y * 128, bn = blockIdx.x * 128;
    const int tid = threadIdx.x;
    const int lr = tid >> 2;       // 0..63
    const int lf = tid & 3;        // float4 index within 16-float k-row
    const int tx = tid & 15, ty = tid >> 4;
    float acc[8][8] = {};
    const int nk = K >> 4;

    float4 a0r, a1r, b0r, b1r;
    // prologue: slab 0
    {
        int r0 = bm + lr, r1 = bm + lr + 64;
        a0r = (r0 < M) ? *(const float4*)(A + (size_t)r0*lda + lf*4) : F4Z;
        a1r = (r1 < M) ? *(const float4*)(A + (size_t)r1*lda + lf*4) : F4Z;
        int s0 = bn + lr, s1 = bn + lr + 64;
        b0r = (s0 < N) ? *(const float4*)(B + (size_t)s0*ldb + lf*4) : F4Z;
        b1r = (s1 < N) ? *(const float4*)(B + (size_t)s1*ldb + lf*4) : F4Z;
        As[0][lf*4+0][lr] = a0r.x; As[0][lf*4+1][lr] = a0r.y;
        As[0][lf*4+2][lr] = a0r.z; As[0][lf*4+3][lr] = a0r.w;
        As[0][lf*4+0][lr+64] = a1r.x; As[0][lf*4+1][lr+64] = a1r.y;
        As[0][lf*4+2][lr+64] = a1r.z; As[0][lf*4+3][lr+64] = a1r.w;
        Bs[0][lf*4+0][lr] = b0r.x; Bs[0][lf*4+1][lr] = b0r.y;
        Bs[0][lf*4+2][lr] = b0r.z; Bs[0][lf*4+3][lr] = b0r.w;
        Bs[0][lf*4+0][lr+64] = b1r.x; Bs[0][lf*4+1][lr+64] = b1r.y;
        Bs[0][lf*4+2][lr+64] = b1r.z; Bs[0][lf*4+3][lr+64] = b1r.w;
    }
    __syncthreads();

    for (int t = 0; t < nk; t++) {
        const int cur = t & 1;
        const bool pre = (t + 1 < nk);
        if (pre) {
            int k0 = (t+1) * 16;
            int r0 = bm + lr, r1 = bm + lr + 64;
            a0r = (r0 < M) ? *(const float4*)(A + (size_t)r0*lda + k0 + lf*4) : F4Z;
            a1r = (r1 < M) ? *(const float4*)(A + (size_t)r1*lda + k0 + lf*4) : F4Z;
            int s0 = bn + lr, s1 = bn + lr + 64;
            b0r = (s0 < N) ? *(const float4*)(B + (size_t)s0*ldb + k0 + lf*4) : F4Z;
            b1r = (s1 < N) ? *(const float4*)(B + (size_t)s1*ldb + k0 + lf*4) : F4Z;
        }
        #pragma unroll
        for (int kk = 0; kk < 16; kk++) {
            float4 a0 = *(const float4*)&As[cur][kk][ty*4];
            float4 a1 = *(const float4*)&As[cur][kk][64 + ty*4];
            float4 b0 = *(const float4*)&Bs[cur][kk][tx*4];
            float4 b1 = *(const float4*)&Bs[cur][kk][64 + tx*4];
            float av[8] = {a0.x,a0.y,a0.z,a0.w,a1.x,a1.y,a1.z,a1.w};
            float bv[8] = {b0.x,b0.y,b0.z,b0.w,b1.x,b1.y,b1.z,b1.w};
            #pragma unroll
            for (int i = 0; i < 8; i++)
                #pragma unroll
                for (int j = 0; j < 8; j++)
                    acc[i][j] = fmaf(av[i], bv[j], acc[i][j]);
        }
        if (pre) {
            const int nx = cur ^ 1;
            As[nx][lf*4+0][lr] = a0r.x; As[nx][lf*4+1][lr] = a0r.y;
            As[nx][lf*4+2][lr] = a0r.z; As[nx][lf*4+3][lr] = a0r.w;
            As[nx][lf*4+0][lr+64] = a1r.x; As[nx][lf*4+1][lr+64] = a1r.y;
            As[nx][lf*4+2][lr+64] = a1r.z; As[nx][lf*4+3][lr+64] = a1r.w;
            Bs[nx][lf*4+0][lr] = b0r.x; Bs[nx][lf*4+1][lr] = b0r.y;
            Bs[nx][lf*4+2][lr] = b0r.z; Bs[nx][lf*4+3][lr] = b0r.w;
            Bs[nx][lf*4+0][lr+64] = b1r.x; Bs[nx][lf*4+1][lr+64] = b1r.y;
            Bs[nx][lf*4+2][lr+64] = b1r.z; Bs[nx][lf*4+3][lr+64] = b1r.w;
        }
        __syncthreads();
    }
    gemm_epilogue(acc, C, M, N, ldc, cB, bias, res, resB, mode, bm, bn, z, tx, ty);
}

// NN: C[m,n] = sum_k A[m,k]*B[k,n]
__global__ void __launch_bounds__(256, 2) gemm_nn128(
    const float* __restrict__ A, const float* __restrict__ B, float* __restrict__ C,
    int M, int N, int K, int lda, int ldb, int ldc,
    long long aB, long long bB, long long cB,
    const float* __restrict__ bias, const float* __restrict__ res, long long resB,
    int mode)
{
    __shared__ float As[2][16][128];
    __shared__ float Bs[2][16][128];
    const int z = blockIdx.z;
    A += (size_t)z * aB; B += (size_t)z * bB;
    const int bm = blockIdx.y * 128, bn = blockIdx.x * 128;
    const int tid = threadIdx.x;
    const int lr = tid >> 2;       // A: 0..63
    const int lf = tid & 3;
    const int kr = tid >> 5;       // B: 0..7
    const int nf = tid & 31;       // B: float4 among 32
    const int tx = tid & 15, ty = tid >> 4;
    float acc[8][8] = {};
    const int nk = K >> 4;

    float4 a0r, a1r, b0r, b1r;
    {
        int r0 = bm + lr, r1 = bm + lr + 64;
        a0r = (r0 < M) ? *(const float4*)(A + (size_t)r0*lda + lf*4) : F4Z;
        a1r = (r1 < M) ? *(const float4*)(A + (size_t)r1*lda + lf*4) : F4Z;
        b0r = *(const float4*)(B + (size_t)kr*ldb + bn + nf*4);
        b1r = *(const float4*)(B + (size_t)(kr+8)*ldb + bn + nf*4);
        As[0][lf*4+0][lr] = a0r.x; As[0][lf*4+1][lr] = a0r.y;
        As[0][lf*4+2][lr] = a0r.z; As[0][lf*4+3][lr] = a0r.w;
        As[0][lf*4+0][lr+64] = a1r.x; As[0][lf*4+1][lr+64] = a1r.y;
        As[0][lf*4+2][lr+64] = a1r.z; As[0][lf*4+3][lr+64] = a1r.w;
        *(float4*)&Bs[0][kr][nf*4]   = b0r;
        *(float4*)&Bs[0][kr+8][nf*4] = b1r;
    }
    __syncthreads();

    for (int t = 0; t < nk; t++) {
        const int cur = t & 1;
        const bool pre = (t + 1 < nk);
        if (pre) {
            int k0 = (t+1) * 16;
            int r0 = bm + lr, r1 = bm + lr + 64;
            a0r = (r0 < M) ? *(const float4*)(A + (size_t)r0*lda + k0 + lf*4) : F4Z;
            a1r = (r1 < M) ? *(const float4*)(A + (size_t)r1*lda + k0 + lf*4) : F4Z;
            b0r = *(const float4*)(B + (size_t)(k0+kr)*ldb + bn + nf*4);
            b1r = *(const float4*)(B + (size_t)(k0+kr+8)*ldb + bn + nf*4);
        }
        #pragma unroll
        for (int kk = 0; kk < 16; kk++) {
            float4 a0 = *(const float4*)&As[cur][kk][ty*4];
            float4 a1 = *(const float4*)&As[cur][kk][64 + ty*4];
            float4 b0 = *(const float4*)&Bs[cur][kk][tx*4];
            float4 b1 = *(const float4*)&Bs[cur][kk][64 + tx*4];
            float av[8] = {a0.x,a0.y,a0.z,a0.w,a1.x,a1.y,a1.z,a1.w};
            float bv[8] = {b0.x,b0.y,b0.z,b0.w,b1.x,b1.y,b1.z,b1.w};
            #pragma unroll
            for (int i = 0; i < 8; i++)
                #pragma unroll
                for (int j = 0; j < 8; j++)
                    acc[i][j] = fmaf(av[i], bv[j], acc[i][j]);
        }
        if (pre) {
            const int nx = cur ^ 1;
            As[nx][lf*4+0][lr] = a0r.x; As[nx][lf*4+1][lr] = a0r.y;
            As[nx][lf*4+2][lr] = a0r.z; As[nx][lf*4+3][lr] = a0r.w;
            As[nx][lf*4+0][lr+64] = a1r.x; As[nx][lf*4+1][lr+64] = a1r.y;
            As[nx][lf*4+2][lr+64] = a1r.z; As[nx][lf*4+3][lr+64] = a1r.w;
            *(float4*)&Bs[nx][kr][nf*4]   = b0r;
            *(float4*)&Bs[nx][kr+8][nf*4] = b1r;
        }
        __syncthreads();
    }
    gemm_epilogue(acc, C, M, N, ldc, cB, bias, res, resB, mode, bm, bn, z, tx, ty);
}

// ---------------- BatchNorm over (B,S) per channel -------------------------
__global__ void bn1_stats(const float* __restrict__ x) {
    int c = blockIdx.x;
    int t = threadIdx.x;
    float s = 0.f, ss = 0.f;
    for (int i = t; i < BS; i += 256) {
        float v = x[(size_t)i*Cdim + c];
        s += v; ss += v*v;
    }
    __shared__ float sha[256], shb[256];
    sha[t] = s; shb[t] = ss; __syncthreads();
    for (int o = 128; o; o >>= 1) {
        if (t < o) { sha[t] += sha[t+o]; shb[t] += shb[t+o]; }
        __syncthreads();
    }
    if (t == 0) {
        float m = sha[0] / (float)BS;
        float var = shb[0] / (float)BS - m*m;
        g_mu[c] = m;
        g_rstd[c] = rsqrtf(var + EPSV);
    }
}

__global__ void bn1_apply(const float* __restrict__ x,
                          const float* __restrict__ g, const float* __restrict__ b) {
    int idx = blockIdx.x * blockDim.x + threadIdx.x;
    if (idx >= BS*Cdim) return;
    int c = idx % Cdim;
    g_xn[idx] = (x[idx] - g_mu[c]) * g_rstd[c] * g[c] + b[c];
}

// ---------------- self-attn small kernels ----------------------------------
__global__ void sa_energy(const float* __restrict__ q, const float* __restrict__ k,
                          float* __restrict__ e) {
    int bh = blockIdx.x; int b = bh >> 3, h = bh & 7;
    __shared__ float qs[Sdim][DHdim+1], ks[Sdim][DHdim+1];
    int t = threadIdx.x;
    for (int idx = t; idx < Sdim*DHdim; idx += 256) {
        int r = idx >> 6, d = idx & 63;
        qs[r][d] = q[(size_t)(b*Sdim + r)*Cdim + h*DHdim + d];
        ks[r][d] = k[(size_t)(b*Sdim + r)*Cdim + h*DHdim + d];
    }
    __syncthreads();
    for (int idx = t; idx < SS; idx += 256) {
        int i = idx / Sdim, j = idx % Sdim;
        float acc = 0.f;
        #pragma unroll
        for (int d = 0; d < DHdim; d++) acc = fmaf(qs[i][d], ks[j][d], acc);
        e[(size_t)bh*SS + idx] = acc;
    }
}

__global__ void bn2_stats(const float* __restrict__ e) {
    int j = blockIdx.x;
    int t = threadIdx.x;
    float s = 0.f, ss = 0.f;
    for (int i = t; i < BH; i += 256) {
        float v = e[(size_t)i*SS + j];
        s += v; ss += v*v;
    }
    __shared__ float sha[256], shb[256];
    sha[t] = s; shb[t] = ss; __syncthreads();
    for (int o = 128; o; o >>= 1) {
        if (t < o) { sha[t] += sha[t+o]; shb[t] += shb[t+o]; }
        __syncthreads();
    }
    if (t == 0) {
        float m = sha[0] / (float)BH;
        float var = shb[0] / (float)BH - m*m;
        g_mu2[j] = m;
        g_rstd2[j] = rsqrtf(var + EPSV);
    }
}

__global__ void sa_softmax(const float* __restrict__ e,
                           const float* __restrict__ pg, const float* __restrict__ pb,
                           float* __restrict__ attn) {
    int row  = blockIdx.x * 8 + (threadIdx.x >> 5);
    int lane = threadIdx.x & 31;
    if (row >= BH*Sdim) return;
    int bh = row / Sdim, i = row % Sdim;
    float val = 0.f, x = -1e30f;
    if (lane < Sdim) {
        int j = i*Sdim + lane;
        float ev = e[(size_t)bh*SS + j];
        val = ((ev - g_mu2[j]) * g_rstd2[j] * pg[j] + pb[j]) * INV_SCALE;
        x = val;
    }
    for (int o = 16; o; o >>= 1) x = fmaxf(x, __shfl_xor_sync(0xffffffffu, x, o));
    float ex = (lane < Sdim) ? expf(val - x) : 0.f;
    float sum = ex;
    for (int o = 16; o; o >>= 1) sum += __shfl_xor_sync(0xffffffffu, sum, o);
    if (lane < Sdim) attn[(size_t)bh*SS + i*Sdim + lane] = ex / sum;
}

__global__ void sa_av(const float* __restrict__ attn, const float* __restrict__ v,
                      float* __restrict__ o) {
    int bh = blockIdx.x; int b = bh >> 3, h = bh & 7;
    __shared__ float as[Sdim][Sdim+1];
    __shared__ float vs[Sdim][DHdim+1];
    int t = threadIdx.x;
    for (int idx = t; idx < SS; idx += 256)
        as[idx / Sdim][idx % Sdim] = attn[(size_t)bh*SS + idx];
    for (int idx = t; idx < Sdim*DHdim; idx += 256) {
        int r = idx >> 6, d = idx & 63;
        vs[r][d] = v[(size_t)(b*Sdim + r)*Cdim + h*DHdim + d];
    }
    __syncthreads();
    for (int idx = t; idx < Sdim*DHdim; idx += 256) {
        int i = idx >> 6, d = idx & 63;
        float acc = 0.f;
        #pragma unroll
        for (int j = 0; j < Sdim; j++) acc = fmaf(as[i][j], vs[j][d], acc);
        o[(size_t)(b*Sdim + i)*Cdim + h*DHdim + d] = acc;
    }
}

// ---------------- LayerNorm (per row), optional SiLU ------------------------
__global__ void ln_kernel(const float* __restrict__ x, float* __restrict__ y,
                          const float* __restrict__ g, const float* __restrict__ bta,
                          int cols, int silu) {
    const int row = blockIdx.x;
    const float* xr = x + (size_t)row*cols;
    float* yr = y + (size_t)row*cols;
    __shared__ float sh[256];
    int t = threadIdx.x;
    float s = 0.f, ss = 0.f;
    for (int c = t; c < cols; c += 256) { float v = xr[c]; s += v; ss += v*v; }
    sh[t] = s; __syncthreads();
    for (int o = 128; o; o >>= 1) { if (t < o) sh[t] += sh[t+o]; __syncthreads(); }
    float mean = sh[0] / (float)cols; __syncthreads();
    sh[t] = ss; __syncthreads();
    for (int o = 128; o; o >>= 1) { if (t < o) sh[t] += sh[t+o]; __syncthreads(); }
    float var = sh[0] / (float)cols - mean*mean;
    float rstd = rsqrtf(var + EPSV);
    for (int c = t; c < cols; c += 256) {
        float v = (xr[c] - mean) * rstd * g[c] + bta[c];
        if (silu) v = v / (1.0f + expf(-v));
        yr[c] = v;
    }
}

// ---------------- softmax over CTX ------------------------------------------
__global__ void ca_softmax(const float* __restrict__ e2, float* __restrict__ attn2) {
    const int row = blockIdx.x;
    const float* er = e2 + (size_t)row * CTXdim;
    float* ar = attn2 + (size_t)row * CTXdim;
    __shared__ float sh[256];
    int t = threadIdx.x;
    float mx = -1e30f;
    for (int j = t; j < CTXdim; j += 256) mx = fmaxf(mx, er[j]);
    sh[t] = mx; __syncthreads();
    for (int o = 128; o; o >>= 1) { if (t < o) sh[t] = fmaxf(sh[t], sh[t+o]); __syncthreads(); }
    mx = sh[0] * INV_SCALE; __syncthreads();
    float sum = 0.f;
    for (int j = t; j < CTXdim; j += 256) {
        float v = expf(er[j]*INV_SCALE - mx);
        ar[j] = v;
        sum += v;
    }
    sh[t] = sum; __syncthreads();
    for (int o = 128; o; o >>= 1) { if (t < o) sh[t] += sh[t+o]; __syncthreads(); }
    float inv = 1.0f / sh[0];
    for (int j = t; j < CTXdim; j += 256) ar[j] *= inv;
}

// ---------------- launch ----------------------------------------------------
extern "C" void kernel_launch(void* const* d_in, const int* in_sizes, int n_in,
                              void* d_out, int out_size) {
    const float* queries  = (const float*)d_in[0];
    const float* contexts = (const float*)d_in[1];
    const float* sa_bn_g  = (const float*)d_in[2];
    const float* sa_bn_b  = (const float*)d_in[3];
    const float* sa_q_w   = (const float*)d_in[4];
    const float* sa_k_w   = (const float*)d_in[5];
    const float* sa_v_w   = (const float*)d_in[6];
    const float* sa_out_w = (const float*)d_in[7];
    const float* sa_out_b = (const float*)d_in[8];
    const float* sa_pre_g = (const float*)d_in[9];
    const float* sa_pre_b = (const float*)d_in[10];
    const float* ca_ln_g  = (const float*)d_in[11];
    const float* ca_ln_b  = (const float*)d_in[12];
    const float* ca_q_w   = (const float*)d_in[13];
    const float* ca_k_w   = (const float*)d_in[14];
    const float* ca_v_w   = (const float*)d_in[15];
    const float* ca_out_w = (const float*)d_in[16];
    const float* ca_out_b = (const float*)d_in[17];
    const float* ff_ln1_g = (const float*)d_in[18];
    const float* ff_ln1_b = (const float*)d_in[19];
    const float* ff_w1    = (const float*)d_in[20];
    const float* ff_ln2_g = (const float*)d_in[21];
    const float* ff_ln2_b = (const float*)d_in[22];
    const float* ff_w2    = (const float*)d_in[23];

    float* out = (float*)d_out;
    float* e2  = out + (size_t)BS*Cdim;

    float *xn,*q,*k,*v,*e,*attn,*o,*xsa,*qn,*q2,*qk,*attn2,*ov2,*o2,*xca,*t1,*t2,*t3;
    cudaGetSymbolAddress((void**)&xn,   g_xn);
    cudaGetSymbolAddress((void**)&q,    g_q);
    cudaGetSymbolAddress((void**)&k,    g_k);
    cudaGetSymbolAddress((void**)&v,    g_v);
    cudaGetSymbolAddress((void**)&e,    g_e);
    cudaGetSymbolAddress((void**)&attn, g_attn);
    cudaGetSymbolAddress((void**)&o,    g_o);
    cudaGetSymbolAddress((void**)&xsa,  g_xsa);
    cudaGetSymbolAddress((void**)&qn,   g_qn);
    cudaGetSymbolAddress((void**)&q2,   g_q2);
    cudaGetSymbolAddress((void**)&qk,   g_qk);
    cudaGetSymbolAddress((void**)&attn2,g_attn2);
    cudaGetSymbolAddress((void**)&ov2,  g_ov2);
    cudaGetSymbolAddress((void**)&o2,   g_o2);
    cudaGetSymbolAddress((void**)&xca,  g_xca);
    cudaGetSymbolAddress((void**)&t1,   g_t1);
    cudaGetSymbolAddress((void**)&t2,   g_t2);
    cudaGetSymbolAddress((void**)&t3,   g_t3);

    const dim3 gProj(4, 16);            // N=512, M=1984
    const int MB = 1984;

    // ---- self attention ----
    bn1_stats<<<Cdim, 256>>>(queries);
    bn1_apply<<<(BS*Cdim + 255)/256, 256>>>(queries, sa_bn_g, sa_bn_b);
    gemm_nt128<<<gProj, 256>>>(xn, sa_q_w, q, MB, 512, 512, 512, 512, 512,
                               0,0,0, nullptr, nullptr, 0, 0);
    gemm_nt128<<<gProj, 256>>>(xn, sa_k_w, k, MB, 512, 512, 512, 512, 512,
                               0,0,0, nullptr, nullptr, 0, 0);
    gemm_nt128<<<gProj, 256>>>(xn, sa_v_w, v, MB, 512, 512, 512, 512, 512,
                               0,0,0, nullptr, nullptr, 0, 0);
    sa_energy<<<BH, 256>>>(q, k, e);
    bn2_stats<<<SS, 256>>>(e);
    sa_softmax<<<(BH*Sdim)/8, 256>>>(e, sa_pre_g, sa_pre_b, attn);
    sa_av<<<BH, 256>>>(attn, v, o);
    gemm_nt128<<<gProj, 256>>>(o, sa_out_w, xsa, MB, 512, 512, 512, 512, 512,
                               0,0,0, sa_out_b, queries, 0, 0);

    // ---- cross attention ----
    ln_kernel<<<BS, 256>>>(xsa, qn, ca_ln_g, ca_ln_b, Cdim, 0);
    gemm_nt128<<<gProj, 256>>>(qn, ca_q_w, q2, MB, 512, 512, 512, 512, 512,
                               0,0,0, nullptr, nullptr, 0, 0);
    // qk[(b,h,s), c] = q2_h (1984x64) @ Kw_h (64x512), per-head NN, mode 1
    gemm_nn128<<<dim3(4, 16, 8), 256>>>(q2, ca_k_w, qk, MB, 512, 64, 512, 512, 512,
                               64LL, 64LL*512, 0, nullptr, nullptr, 0, 1);
    // e2[(b,h,s), ctx] = qk_b (248x512) @ ctx_b^T (2048x512), batched NT
    gemm_nt128<<<dim3(16, 2, 64), 256>>>(qk, contexts, e2, 248, 2048, 512, 512, 512, 2048,
                               248LL*512, 2048LL*512, 248LL*2048, nullptr, nullptr, 0, 0);
    ca_softmax<<<BH*Sdim, 256>>>(e2, attn2);
    // ov2[(b,s), h*512+c] = attn2_b (248x2048) @ ctx_b (2048x512), batched NN, mode 2
    gemm_nn128<<<dim3(4, 2, 64), 256>>>(attn2, contexts, ov2, 248, 512, 2048, 2048, 512, 512,
                               248LL*2048, 2048LL*512, 31LL*4096, nullptr, nullptr, 0, 2);
    // o2[bi, h*64+e] = ov2_h (1984x512) @ Vw_h^T (64x512), per-head NT, N=64
    gemm_nt128<<<dim3(1, 16, 8), 256>>>(ov2, ca_v_w, o2, MB, 64, 512, 4096, 512, 512,
                               512LL, 64LL*512, 64LL, nullptr, nullptr, 0, 0);
    gemm_nt128<<<gProj, 256>>>(o2, ca_out_w, xca, MB, 512, 512, 512, 512, 512,
                               0,0,0, ca_out_b, xsa, 0, 0);

    // ---- FFN ----
    ln_kernel<<<BS, 256>>>(xca, t1, ff_ln1_g, ff_ln1_b, Cdim, 1);
    gemm_nt128<<<dim3(8, 16), 256>>>(t1, ff_w1, t2, MB, 1024, 512, 512, 512, 1024,
                               0,0,0, nullptr, nullptr, 0, 0);
    ln_kernel<<<BS, 256>>>(t2, t3, ff_ln2_g, ff_ln2_b, 2*Cdim, 1);
    gemm_nt128<<<gProj, 256>>>(t3, ff_w2, out, MB, 512, 1024, 1024, 1024, 512,
                               0,0,0, nullptr, xca, 0, 0);
}

// round 4
// speedup vs baseline: 5.4549x; 1.7845x over previous
#include <cuda_runtime.h>
#include <math.h>

#define Bdim 64
#define Sdim 31
#define CTXdim 2048
#define Cdim 512
#define Hdim 8
#define DHdim 64
#define BS (Bdim*Sdim)        // 1984
#define BH (Bdim*Hdim)        // 512
#define SS (Sdim*Sdim)        // 961
#define EPSV 1e-5f
#define INV_SCALE 0.04419417382415922f   // 1/sqrt(512)
#define SA 136                // smem row stride (words); 136 % 32 == 8 -> conflict-free frags

// ---------------- scratch (device globals; no runtime allocation) ----------
__device__ float g_xn[BS*Cdim];
__device__ float g_q[BS*Cdim];
__device__ float g_k[BS*Cdim];
__device__ float g_v[BS*Cdim];
__device__ float g_e[BH*SS];
__device__ float g_attn[BH*SS];
__device__ float g_o[BS*Cdim];
__device__ float g_xsa[BS*Cdim];
__device__ float g_qn[BS*Cdim];
__device__ float g_q2[BS*Cdim];
__device__ float g_qk[(size_t)BH*Sdim*Cdim];        // (b,h,s) x 512
__device__ float g_attn2[(size_t)BH*Sdim*CTXdim];
__device__ float g_ov2[(size_t)BS*Hdim*Cdim];       // (b,s) x (h*512+c)
__device__ float g_o2[BS*Cdim];
__device__ float g_xca[BS*Cdim];
__device__ float g_t1[BS*Cdim];
__device__ float g_t2[BS*2*Cdim];
__device__ float g_t3[BS*2*Cdim];
__device__ float g_mu[Cdim], g_rstd[Cdim];
__device__ float g_mu2[SS], g_rstd2[SS];

#define F4Z make_float4(0.f,0.f,0.f,0.f)

// ---------------- tf32 helpers ---------------------------------------------
__device__ __forceinline__ unsigned f2tf(float x) {
    unsigned r;
    asm("cvt.rna.tf32.f32 %0, %1;" : "=r"(r) : "f"(x));
    return r;
}

__device__ __forceinline__ void mma8(float c[4], const unsigned a[4], const unsigned b[2]) {
    asm("mma.sync.aligned.m16n8k8.row.col.f32.tf32.tf32.f32 "
        "{%0,%1,%2,%3}, {%4,%5,%6,%7}, {%8,%9}, {%0,%1,%2,%3};"
        : "+f"(c[0]), "+f"(c[1]), "+f"(c[2]), "+f"(c[3])
        : "r"(a[0]), "r"(a[1]), "r"(a[2]), "r"(a[3]), "r"(b[0]), "r"(b[1]));
}

// transpose-store a 16-k slab fragment pair into As[k][m] (tf32 bits)
__device__ __forceinline__ void stq(unsigned (*S)[SA], int lf, int lr,
                                    float4 v0, float4 v1) {
    S[lf*4+0][lr] = f2tf(v0.x); S[lf*4+1][lr] = f2tf(v0.y);
    S[lf*4+2][lr] = f2tf(v0.z); S[lf*4+3][lr] = f2tf(v0.w);
    S[lf*4+0][lr+64] = f2tf(v1.x); S[lf*4+1][lr+64] = f2tf(v1.y);
    S[lf*4+2][lr+64] = f2tf(v1.z); S[lf*4+3][lr+64] = f2tf(v1.w);
}

// one k16 slab of warp-tile MMAs. As/Bs are [16][SA] for the current buffer.
__device__ __forceinline__ void compute_k16(
    const unsigned (*As)[SA], const unsigned (*Bs)[SA],
    float acc[4][4][4], int wm, int wn, int g, int t)
{
    #pragma unroll
    for (int ks = 0; ks < 2; ks++) {
        const int k0 = ks*8;
        unsigned ua[4][4], ub[4][2];
        #pragma unroll
        for (int mt = 0; mt < 4; mt++) {
            int mb = wm + mt*16 + g;
            ua[mt][0] = As[k0+t][mb];
            ua[mt][1] = As[k0+t][mb+8];
            ua[mt][2] = As[k0+4+t][mb];
            ua[mt][3] = As[k0+4+t][mb+8];
        }
        #pragma unroll
        for (int nt = 0; nt < 4; nt++) {
            int nb = wn + nt*8 + g;
            ub[nt][0] = Bs[k0+t][nb];
            ub[nt][1] = Bs[k0+4+t][nb];
        }
        #pragma unroll
        for (int mt = 0; mt < 4; mt++)
            #pragma unroll
            for (int nt = 0; nt < 4; nt++)
                mma8(acc[mt][nt], ua[mt], ub[nt]);
    }
}

// epilogue: mode 0 plain (+bias,+res); mode 1 qk permute; mode 2 ov2 permute
__device__ __forceinline__ void tf_epilogue(
    float acc[4][4][4], float* __restrict__ C, int M, int N, int ldc, long long cB,
    const float* __restrict__ bias, const float* __restrict__ res, long long resB,
    int mode, int bm, int bn, int z, int wm, int wn, int g, int t)
{
    const float* resp = res ? res + (size_t)z*resB : nullptr;
    #pragma unroll
    for (int mt = 0; mt < 4; mt++) {
        #pragma unroll
        for (int hh = 0; hh < 2; hh++) {
            int m = bm + wm + mt*16 + g + hh*8;
            if (m >= M) continue;
            size_t rowbase;
            if (mode == 0)      rowbase = (size_t)z*cB + (size_t)m*ldc;
            else if (mode == 1) rowbase = (size_t)((m/31)*248 + z*31 + (m%31)) * ldc;
            else                rowbase = (size_t)z*cB + (size_t)(m%31)*4096 + (size_t)(m/31)*512;
            #pragma unroll
            for (int nt = 0; nt < 4; nt++) {
                #pragma unroll
                for (int jj = 0; jj < 2; jj++) {
                    int n = bn + wn + nt*8 + 2*t + jj;
                    if (n >= N) continue;
                    float v = acc[mt][nt][hh*2+jj];
                    if (bias) v += bias[n];
                    if (resp) v += resp[(size_t)m*ldc + n];
                    C[rowbase + n] = v;
                }
            }
        }
    }
}

// NT: C[m,n] = sum_k A[m,k]*B[n,k], tf32 tensor cores
__global__ void __launch_bounds__(256, 2) tgemm_nt(
    const float* __restrict__ A, const float* __restrict__ B, float* __restrict__ C,
    int M, int N, int K, int lda, int ldb, int ldc,
    long long aB, long long bB, long long cB,
    const float* __restrict__ bias, const float* __restrict__ res, long long resB,
    int mode)
{
    __shared__ unsigned As[2][16][SA];
    __shared__ unsigned Bs[2][16][SA];
    const int z = blockIdx.z;
    A += (size_t)z*aB; B += (size_t)z*bB;
    const int bm = blockIdx.y*128, bn = blockIdx.x*128;
    const int tid = threadIdx.x;
    const int lr = tid>>2, lf = tid&3;
    const int lane = tid&31, g = lane>>2, t = lane&3;
    const int warp = tid>>5;
    const int wm = (warp>>2)*64, wn = (warp&3)*32;
    float acc[4][4][4] = {};
    const int nk = K>>4;

    float4 a0r, a1r, b0r, b1r;
    {
        int r0 = bm+lr, r1 = bm+lr+64;
        a0r = (r0<M) ? *(const float4*)(A+(size_t)r0*lda+lf*4) : F4Z;
        a1r = (r1<M) ? *(const float4*)(A+(size_t)r1*lda+lf*4) : F4Z;
        int s0 = bn+lr, s1 = bn+lr+64;
        b0r = (s0<N) ? *(const float4*)(B+(size_t)s0*ldb+lf*4) : F4Z;
        b1r = (s1<N) ? *(const float4*)(B+(size_t)s1*ldb+lf*4) : F4Z;
        stq(As[0], lf, lr, a0r, a1r);
        stq(Bs[0], lf, lr, b0r, b1r);
    }
    __syncthreads();

    for (int it = 0; it < nk; it++) {
        const int cur = it & 1;
        const bool pre = (it+1 < nk);
        if (pre) {
            int k0 = (it+1)*16;
            int r0 = bm+lr, r1 = bm+lr+64;
            a0r = (r0<M) ? *(const float4*)(A+(size_t)r0*lda+k0+lf*4) : F4Z;
            a1r = (r1<M) ? *(const float4*)(A+(size_t)r1*lda+k0+lf*4) : F4Z;
            int s0 = bn+lr, s1 = bn+lr+64;
            b0r = (s0<N) ? *(const float4*)(B+(size_t)s0*ldb+k0+lf*4) : F4Z;
            b1r = (s1<N) ? *(const float4*)(B+(size_t)s1*ldb+k0+lf*4) : F4Z;
        }
        compute_k16(As[cur], Bs[cur], acc, wm, wn, g, t);
        if (pre) {
            const int nx = cur ^ 1;
            stq(As[nx], lf, lr, a0r, a1r);
            stq(Bs[nx], lf, lr, b0r, b1r);
        }
        __syncthreads();
    }
    tf_epilogue(acc, C, M, N, ldc, cB, bias, res, resB, mode, bm, bn, z, wm, wn, g, t);
}

// NN: C[m,n] = sum_k A[m,k]*B[k,n], tf32 tensor cores
__global__ void __launch_bounds__(256, 2) tgemm_nn(
    const float* __restrict__ A, const float* __restrict__ B, float* __restrict__ C,
    int M, int N, int K, int lda, int ldb, int ldc,
    long long aB, long long bB, long long cB,
    const float* __restrict__ bias, const float* __restrict__ res, long long resB,
    int mode)
{
    __shared__ unsigned As[2][16][SA];
    __shared__ unsigned Bs[2][16][SA];
    const int z = blockIdx.z;
    A += (size_t)z*aB; B += (size_t)z*bB;
    const int bm = blockIdx.y*128, bn = blockIdx.x*128;
    const int tid = threadIdx.x;
    const int lr = tid>>2, lf = tid&3;
    const int kr = tid>>5, nf = tid&31;
    const int lane = tid&31, g = lane>>2, t = lane&3;
    const int warp = tid>>5;
    const int wm = (warp>>2)*64, wn = (warp&3)*32;
    float acc[4][4][4] = {};
    const int nk = K>>4;

    float4 a0r, a1r, b0r, b1r;
    {
        int r0 = bm+lr, r1 = bm+lr+64;
        a0r = (r0<M) ? *(const float4*)(A+(size_t)r0*lda+lf*4) : F4Z;
        a1r = (r1<M) ? *(const float4*)(A+(size_t)r1*lda+lf*4) : F4Z;
        b0r = *(const float4*)(B + (size_t)kr*ldb + bn + nf*4);
        b1r = *(const float4*)(B + (size_t)(kr+8)*ldb + bn + nf*4);
        stq(As[0], lf, lr, a0r, a1r);
        uint4 u0 = make_uint4(f2tf(b0r.x), f2tf(b0r.y), f2tf(b0r.z), f2tf(b0r.w));
        uint4 u1 = make_uint4(f2tf(b1r.x), f2tf(b1r.y), f2tf(b1r.z), f2tf(b1r.w));
        *(uint4*)&Bs[0][kr][nf*4]   = u0;
        *(uint4*)&Bs[0][kr+8][nf*4] = u1;
    }
    __syncthreads();

    for (int it = 0; it < nk; it++) {
        const int cur = it & 1;
        const bool pre = (it+1 < nk);
        if (pre) {
            int k0 = (it+1)*16;
            int r0 = bm+lr, r1 = bm+lr+64;
            a0r = (r0<M) ? *(const float4*)(A+(size_t)r0*lda+k0+lf*4) : F4Z;
            a1r = (r1<M) ? *(const float4*)(A+(size_t)r1*lda+k0+lf*4) : F4Z;
            b0r = *(const float4*)(B + (size_t)(k0+kr)*ldb + bn + nf*4);
            b1r = *(const float4*)(B + (size_t)(k0+kr+8)*ldb + bn + nf*4);
        }
        compute_k16(As[cur], Bs[cur], acc, wm, wn, g, t);
        if (pre) {
            const int nx = cur ^ 1;
            stq(As[nx], lf, lr, a0r, a1r);
            uint4 u0 = make_uint4(f2tf(b0r.x), f2tf(b0r.y), f2tf(b0r.z), f2tf(b0r.w));
            uint4 u1 = make_uint4(f2tf(b1r.x), f2tf(b1r.y), f2tf(b1r.z), f2tf(b1r.w));
            *(uint4*)&Bs[nx][kr][nf*4]   = u0;
            *(uint4*)&Bs[nx][kr+8][nf*4] = u1;
        }
        __syncthreads();
    }
    tf_epilogue(acc, C, M, N, ldc, cB, bias, res, resB, mode, bm, bn, z, wm, wn, g, t);
}

// ---------------- BatchNorm over (B,S) per channel -------------------------
__global__ void bn1_stats(const float* __restrict__ x) {
    int c = blockIdx.x;
    int t = threadIdx.x;
    float s = 0.f, ss = 0.f;
    for (int i = t; i < BS; i += 256) {
        float v = x[(size_t)i*Cdim + c];
        s += v; ss += v*v;
    }
    __shared__ float sha[256], shb[256];
    sha[t] = s; shb[t] = ss; __syncthreads();
    for (int o = 128; o; o >>= 1) {
        if (t < o) { sha[t] += sha[t+o]; shb[t] += shb[t+o]; }
        __syncthreads();
    }
    if (t == 0) {
        float m = sha[0] / (float)BS;
        float var = shb[0] / (float)BS - m*m;
        g_mu[c] = m;
        g_rstd[c] = rsqrtf(var + EPSV);
    }
}

__global__ void bn1_apply(const float* __restrict__ x,
                          const float* __restrict__ g, const float* __restrict__ b) {
    int idx = blockIdx.x * blockDim.x + threadIdx.x;
    if (idx >= BS*Cdim) return;
    int c = idx % Cdim;
    g_xn[idx] = (x[idx] - g_mu[c]) * g_rstd[c] * g[c] + b[c];
}

// ---------------- self-attn small kernels ----------------------------------
__global__ void sa_energy(const float* __restrict__ q, const float* __restrict__ k,
                          float* __restrict__ e) {
    int bh = blockIdx.x; int b = bh >> 3, h = bh & 7;
    __shared__ float qs[Sdim][DHdim+1], ks[Sdim][DHdim+1];
    int t = threadIdx.x;
    for (int idx = t; idx < Sdim*DHdim; idx += 256) {
        int r = idx >> 6, d = idx & 63;
        qs[r][d] = q[(size_t)(b*Sdim + r)*Cdim + h*DHdim + d];
        ks[r][d] = k[(size_t)(b*Sdim + r)*Cdim + h*DHdim + d];
    }
    __syncthreads();
    for (int idx = t; idx < SS; idx += 256) {
        int i = idx / Sdim, j = idx % Sdim;
        float acc = 0.f;
        #pragma unroll
        for (int d = 0; d < DHdim; d++) acc = fmaf(qs[i][d], ks[j][d], acc);
        e[(size_t)bh*SS + idx] = acc;
    }
}

__global__ void bn2_stats(const float* __restrict__ e) {
    int j = blockIdx.x;
    int t = threadIdx.x;
    float s = 0.f, ss = 0.f;
    for (int i = t; i < BH; i += 256) {
        float v = e[(size_t)i*SS + j];
        s += v; ss += v*v;
    }
    __shared__ float sha[256], shb[256];
    sha[t] = s; shb[t] = ss; __syncthreads();
    for (int o = 128; o; o >>= 1) {
        if (t < o) { sha[t] += sha[t+o]; shb[t] += shb[t+o]; }
        __syncthreads();
    }
    if (t == 0) {
        float m = sha[0] / (float)BH;
        float var = shb[0] / (float)BH - m*m;
        g_mu2[j] = m;
        g_rstd2[j] = rsqrtf(var + EPSV);
    }
}

__global__ void sa_softmax(const float* __restrict__ e,
                           const float* __restrict__ pg, const float* __restrict__ pb,
                           float* __restrict__ attn) {
    int row  = blockIdx.x * 8 + (threadIdx.x >> 5);
    int lane = threadIdx.x & 31;
    if (row >= BH*Sdim) return;
    int bh = row / Sdim, i = row % Sdim;
    float val = 0.f, x = -1e30f;
    if (lane < Sdim) {
        int j = i*Sdim + lane;
        float ev = e[(size_t)bh*SS + j];
        val = ((ev - g_mu2[j]) * g_rstd2[j] * pg[j] + pb[j]) * INV_SCALE;
        x = val;
    }
    for (int o = 16; o; o >>= 1) x = fmaxf(x, __shfl_xor_sync(0xffffffffu, x, o));
    float ex = (lane < Sdim) ? expf(val - x) : 0.f;
    float sum = ex;
    for (int o = 16; o; o >>= 1) sum += __shfl_xor_sync(0xffffffffu, sum, o);
    if (lane < Sdim) attn[(size_t)bh*SS + i*Sdim + lane] = ex / sum;
}

__global__ void sa_av(const float* __restrict__ attn, const float* __restrict__ v,
                      float* __restrict__ o) {
    int bh = blockIdx.x; int b = bh >> 3, h = bh & 7;
    __shared__ float as[Sdim][Sdim+1];
    __shared__ float vs[Sdim][DHdim+1];
    int t = threadIdx.x;
    for (int idx = t; idx < SS; idx += 256)
        as[idx / Sdim][idx % Sdim] = attn[(size_t)bh*SS + idx];
    for (int idx = t; idx < Sdim*DHdim; idx += 256) {
        int r = idx >> 6, d = idx & 63;
        vs[r][d] = v[(size_t)(b*Sdim + r)*Cdim + h*DHdim + d];
    }
    __syncthreads();
    for (int idx = t; idx < Sdim*DHdim; idx += 256) {
        int i = idx >> 6, d = idx & 63;
        float acc = 0.f;
        #pragma unroll
        for (int j = 0; j < Sdim; j++) acc = fmaf(as[i][j], vs[j][d], acc);
        o[(size_t)(b*Sdim + i)*Cdim + h*DHdim + d] = acc;
    }
}

// ---------------- LayerNorm (per row), optional SiLU ------------------------
__global__ void ln_kernel(const float* __restrict__ x, float* __restrict__ y,
                          const float* __restrict__ g, const float* __restrict__ bta,
                          int cols, int silu) {
    const int row = blockIdx.x;
    const float* xr = x + (size_t)row*cols;
    float* yr = y + (size_t)row*cols;
    __shared__ float sh[256];
    int t = threadIdx.x;
    float s = 0.f, ss = 0.f;
    for (int c = t; c < cols; c += 256) { float v = xr[c]; s += v; ss += v*v; }
    sh[t] = s; __syncthreads();
    for (int o = 128; o; o >>= 1) { if (t < o) sh[t] += sh[t+o]; __syncthreads(); }
    float mean = sh[0] / (float)cols; __syncthreads();
    sh[t] = ss; __syncthreads();
    for (int o = 128; o; o >>= 1) { if (t < o) sh[t] += sh[t+o]; __syncthreads(); }
    float var = sh[0] / (float)cols - mean*mean;
    float rstd = rsqrtf(var + EPSV);
    for (int c = t; c < cols; c += 256) {
        float v = (xr[c] - mean) * rstd * g[c] + bta[c];
        if (silu) v = v / (1.0f + expf(-v));
        yr[c] = v;
    }
}

// ---------------- softmax over CTX ------------------------------------------
__global__ void ca_softmax(const float* __restrict__ e2, float* __restrict__ attn2) {
    const int row = blockIdx.x;
    const float* er = e2 + (size_t)row * CTXdim;
    float* ar = attn2 + (size_t)row * CTXdim;
    __shared__ float sh[256];
    int t = threadIdx.x;
    float mx = -1e30f;
    for (int j = t; j < CTXdim; j += 256) mx = fmaxf(mx, er[j]);
    sh[t] = mx; __syncthreads();
    for (int o = 128; o; o >>= 1) { if (t < o) sh[t] = fmaxf(sh[t], sh[t+o]); __syncthreads(); }
    mx = sh[0] * INV_SCALE; __syncthreads();
    float sum = 0.f;
    for (int j = t; j < CTXdim; j += 256) {
        float v = expf(er[j]*INV_SCALE - mx);
        ar[j] = v;
        sum += v;
    }
    sh[t] = sum; __syncthreads();
    for (int o = 128; o; o >>= 1) { if (t < o) sh[t] += sh[t+o]; __syncthreads(); }
    float inv = 1.0f / sh[0];
    for (int j = t; j < CTXdim; j += 256) ar[j] *= inv;
}

// ---------------- launch ----------------------------------------------------
extern "C" void kernel_launch(void* const* d_in, const int* in_sizes, int n_in,
                              void* d_out, int out_size) {
    const float* queries  = (const float*)d_in[0];
    const float* contexts = (const float*)d_in[1];
    const float* sa_bn_g  = (const float*)d_in[2];
    const float* sa_bn_b  = (const float*)d_in[3];
    const float* sa_q_w   = (const float*)d_in[4];
    const float* sa_k_w   = (const float*)d_in[5];
    const float* sa_v_w   = (const float*)d_in[6];
    const float* sa_out_w = (const float*)d_in[7];
    const float* sa_out_b = (const float*)d_in[8];
    const float* sa_pre_g = (const float*)d_in[9];
    const float* sa_pre_b = (const float*)d_in[10];
    const float* ca_ln_g  = (const float*)d_in[11];
    const float* ca_ln_b  = (const float*)d_in[12];
    const float* ca_q_w   = (const float*)d_in[13];
    const float* ca_k_w   = (const float*)d_in[14];
    const float* ca_v_w   = (const float*)d_in[15];
    const float* ca_out_w = (const float*)d_in[16];
    const float* ca_out_b = (const float*)d_in[17];
    const float* ff_ln1_g = (const float*)d_in[18];
    const float* ff_ln1_b = (const float*)d_in[19];
    const float* ff_w1    = (const float*)d_in[20];
    const float* ff_ln2_g = (const float*)d_in[21];
    const float* ff_ln2_b = (const float*)d_in[22];
    const float* ff_w2    = (const float*)d_in[23];

    float* out = (float*)d_out;
    float* e2  = out + (size_t)BS*Cdim;

    float *xn,*q,*k,*v,*e,*attn,*o,*xsa,*qn,*q2,*qk,*attn2,*ov2,*o2,*xca,*t1,*t2,*t3;
    cudaGetSymbolAddress((void**)&xn,   g_xn);
    cudaGetSymbolAddress((void**)&q,    g_q);
    cudaGetSymbolAddress((void**)&k,    g_k);
    cudaGetSymbolAddress((void**)&v,    g_v);
    cudaGetSymbolAddress((void**)&e,    g_e);
    cudaGetSymbolAddress((void**)&attn, g_attn);
    cudaGetSymbolAddress((void**)&o,    g_o);
    cudaGetSymbolAddress((void**)&xsa,  g_xsa);
    cudaGetSymbolAddress((void**)&qn,   g_qn);
    cudaGetSymbolAddress((void**)&q2,   g_q2);
    cudaGetSymbolAddress((void**)&qk,   g_qk);
    cudaGetSymbolAddress((void**)&attn2,g_attn2);
    cudaGetSymbolAddress((void**)&ov2,  g_ov2);
    cudaGetSymbolAddress((void**)&o2,   g_o2);
    cudaGetSymbolAddress((void**)&xca,  g_xca);
    cudaGetSymbolAddress((void**)&t1,   g_t1);
    cudaGetSymbolAddress((void**)&t2,   g_t2);
    cudaGetSymbolAddress((void**)&t3,   g_t3);

    const dim3 gProj(4, 16);            // N=512, M=1984
    const int MB = 1984;

    // ---- self attention ----
    bn1_stats<<<Cdim, 256>>>(queries);
    bn1_apply<<<(BS*Cdim + 255)/256, 256>>>(queries, sa_bn_g, sa_bn_b);
    tgemm_nt<<<gProj, 256>>>(xn, sa_q_w, q, MB, 512, 512, 512, 512, 512,
                             0,0,0, nullptr, nullptr, 0, 0);
    tgemm_nt<<<gProj, 256>>>(xn, sa_k_w, k, MB, 512, 512, 512, 512, 512,
                             0,0,0, nullptr, nullptr, 0, 0);
    tgemm_nt<<<gProj, 256>>>(xn, sa_v_w, v, MB, 512, 512, 512, 512, 512,
                             0,0,0, nullptr, nullptr, 0, 0);
    sa_energy<<<BH, 256>>>(q, k, e);
    bn2_stats<<<SS, 256>>>(e);
    sa_softmax<<<(BH*Sdim)/8, 256>>>(e, sa_pre_g, sa_pre_b, attn);
    sa_av<<<BH, 256>>>(attn, v, o);
    tgemm_nt<<<gProj, 256>>>(o, sa_out_w, xsa, MB, 512, 512, 512, 512, 512,
                             0,0,0, sa_out_b, queries, 0, 0);

    // ---- cross attention ----
    ln_kernel<<<BS, 256>>>(xsa, qn, ca_ln_g, ca_ln_b, Cdim, 0);
    tgemm_nt<<<gProj, 256>>>(qn, ca_q_w, q2, MB, 512, 512, 512, 512, 512,
                             0,0,0, nullptr, nullptr, 0, 0);
    // qk[(b,h,s), c] = q2_h (1984x64) @ Kw_h (64x512), per-head NN, mode 1
    tgemm_nn<<<dim3(4, 16, 8), 256>>>(q2, ca_k_w, qk, MB, 512, 64, 512, 512, 512,
                             64LL, 64LL*512, 0, nullptr, nullptr, 0, 1);
    // e2[(b,h,s), ctx] = qk_b (248x512) @ ctx_b^T (2048x512), batched NT
    tgemm_nt<<<dim3(16, 2, 64), 256>>>(qk, contexts, e2, 248, 2048, 512, 512, 512, 2048,
                             248LL*512, 2048LL*512, 248LL*2048, nullptr, nullptr, 0, 0);
    ca_softmax<<<BH*Sdim, 256>>>(e2, attn2);
    // ov2[(b,s), h*512+c] = attn2_b (248x2048) @ ctx_b (2048x512), batched NN, mode 2
    tgemm_nn<<<dim3(4, 2, 64), 256>>>(attn2, contexts, ov2, 248, 512, 2048, 2048, 512, 512,
                             248LL*2048, 2048LL*512, 31LL*4096, nullptr, nullptr, 0, 2);
    // o2[bi, h*64+e] = ov2_h (1984x512) @ Vw_h^T (64x512), per-head NT, N=64
    tgemm_nt<<<dim3(1, 16, 8), 256>>>(ov2, ca_v_w, o2, MB, 64, 512, 4096, 512, 512,
                             512LL, 64LL*512, 64LL, nullptr, nullptr, 0, 0);
    tgemm_nt<<<gProj, 256>>>(o2, ca_out_w, xca, MB, 512, 512, 512, 512, 512,
                             0,0,0, ca_out_b, xsa, 0, 0);

    // ---- FFN ----
    ln_kernel<<<BS, 256>>>(xca, t1, ff_ln1_g, ff_ln1_b, Cdim, 1);
    tgemm_nt<<<dim3(8, 16), 256>>>(t1, ff_w1, t2, MB, 1024, 512, 512, 512, 1024,
                             0,0,0, nullptr, nullptr, 0, 0);
    ln_kernel<<<BS, 256>>>(t2, t3, ff_ln2_g, ff_ln2_b, 2*Cdim, 1);
    tgemm_nt<<<gProj, 256>>>(t3, ff_w2, out, MB, 512, 1024, 1024, 1024, 512,
                             0,0,0, nullptr, xca, 0, 0);
}